// round 3
// baseline (speedup 1.0000x reference)
#include <cuda_runtime.h>

#define Xd   256
#define Bd   64
#define Td   2048
#define Cc   32      // chunk length (power of 2; Mc = M^Cc via 5 squarings)
#define NCc  64      // number of chunks = Td/Cc
#define YHd  64
#define ZHd  16

// ---------------- device scratch (no runtime allocation allowed) ----------------
__device__ float g_drive[Td*Bd*Xd];   // d_t = drive_t + A_b, layout [t][b][x]
__device__ float g_Xst [Td*Bd*Xd];    // pre-update states x_t, layout [t][b][x]
__device__ float g_M   [Xd*Xd];       // M = A_w^T (row-major [j][i])
__device__ float g_P0  [Xd*Xd];
__device__ float g_P1  [Xd*Xd];
__device__ float g_E   [NCc*Bd*Xd];   // chunk end states (zero-init chunk scan)
__device__ float g_X0  [NCc*Bd*Xd];   // true chunk initial states
__device__ float g_Cy1T[Xd*Xd];       // Cy1_w^T  [j][o]
__device__ float g_Cz1T[Xd*Xd];
__device__ float g_Cy2T[Xd*YHd];      // Cy2_w^T  [j][o]
__device__ float g_Cz2T[Xd*ZHd];
__device__ float g_WinT[96*Xd];       // concat(K_w, Bm_w)^T  [j][x]
__device__ float g_bias[Xd];          // K_b + Bm_b + A_b

__device__ __forceinline__ float sigm(float v) { return 1.f / (1.f + __expf(-v)); }

// ---------------- setup: transpose weights into GEMM-friendly layouts ----------------
__global__ __launch_bounds__(256) void setup_kernel(
    const float* __restrict__ A_w,  const float* __restrict__ A_b,
    const float* __restrict__ K_w,  const float* __restrict__ K_b,
    const float* __restrict__ Bm_w, const float* __restrict__ Bm_b,
    const float* __restrict__ Cy1_w, const float* __restrict__ Cz1_w,
    const float* __restrict__ Cy2_w, const float* __restrict__ Cz2_w)
{
    int n = blockIdx.x * 256 + threadIdx.x;
    int stride = gridDim.x * 256;
    for (int i = n; i < Xd*Xd; i += stride) {
        int j = i >> 8, k = i & 255;        // dst [j][k] = src [k][j]
        g_M[i]    = A_w  [k*Xd + j];
        g_Cy1T[i] = Cy1_w[k*Xd + j];
        g_Cz1T[i] = Cz1_w[k*Xd + j];
    }
    for (int i = n; i < Xd*YHd; i += stride) { int j = i >> 6, o = i & 63; g_Cy2T[i] = Cy2_w[o*Xd + j]; }
    for (int i = n; i < Xd*ZHd; i += stride) { int j = i >> 4, o = i & 15; g_Cz2T[i] = Cz2_w[o*Xd + j]; }
    for (int i = n; i < 96*Xd;  i += stride) {
        int j = i >> 8, x = i & 255;
        g_WinT[i] = (j < 64) ? K_w[x*64 + j] : Bm_w[x*32 + (j - 64)];
    }
    for (int i = n; i < Xd; i += stride) g_bias[i] = K_b[i] + Bm_b[i] + A_b[i];
}

// ---------------- drive: d[t][b][x] = y_t·K^T + u_t·Bm^T + (K_b+Bm_b+A_b) ----------------
__global__ __launch_bounds__(256) void drive_kernel(
    const float* __restrict__ y, const float* __restrict__ u)
{
    __shared__ float sIn[64*96];
    int t = blockIdx.x, tid = threadIdx.x;
    for (int m = tid; m < 64*64; m += 256) { int b = m >> 6, c = m & 63; sIn[b*96 + c]      = y[(b*Td + t)*64 + c]; }
    for (int m = tid; m < 64*32; m += 256) { int b = m >> 5, c = m & 31; sIn[b*96 + 64 + c] = u[(b*Td + t)*32 + c]; }
    __syncthreads();
    int tr = tid >> 5, tc = tid & 31;   // 8 row-groups of 8 rows, 32 col-groups of 8 cols
    float acc[8][8];
    float4 b0 = *(const float4*)&g_bias[tc*8];
    float4 b1 = *(const float4*)&g_bias[tc*8 + 4];
    #pragma unroll
    for (int r = 0; r < 8; r++) {
        acc[r][0]=b0.x; acc[r][1]=b0.y; acc[r][2]=b0.z; acc[r][3]=b0.w;
        acc[r][4]=b1.x; acc[r][5]=b1.y; acc[r][6]=b1.z; acc[r][7]=b1.w;
    }
    #pragma unroll 2
    for (int j = 0; j < 96; j++) {
        float4 w0 = *(const float4*)&g_WinT[j*Xd + tc*8];
        float4 w1 = *(const float4*)&g_WinT[j*Xd + tc*8 + 4];
        #pragma unroll
        for (int r = 0; r < 8; r++) {
            float v = sIn[(tr*8 + r)*96 + j];
            acc[r][0]+=v*w0.x; acc[r][1]+=v*w0.y; acc[r][2]+=v*w0.z; acc[r][3]+=v*w0.w;
            acc[r][4]+=v*w1.x; acc[r][5]+=v*w1.y; acc[r][6]+=v*w1.z; acc[r][7]+=v*w1.w;
        }
    }
    float* dp = &g_drive[t*Bd*Xd];
    #pragma unroll
    for (int r = 0; r < 8; r++) {
        int b = tr*8 + r;
        float4 o0 = {acc[r][0],acc[r][1],acc[r][2],acc[r][3]};
        float4 o1 = {acc[r][4],acc[r][5],acc[r][6],acc[r][7]};
        *(float4*)&dp[b*Xd + tc*8]     = o0;
        *(float4*)&dp[b*Xd + tc*8 + 4] = o1;
    }
}

// ---------------- matsq: Q = P·P (256x256 row-major) ----------------
__global__ __launch_bounds__(256) void matsq_kernel(
    const float* __restrict__ P, float* __restrict__ Q)
{
    __shared__ float sL[64*68];
    int i0 = (blockIdx.x >> 2) * 64, k0 = (blockIdx.x & 3) * 64;
    int tid = threadIdx.x, tr = tid >> 4, tc = tid & 15;
    float acc[4][4] = {};
    for (int jb = 0; jb < 4; jb++) {
        for (int m = tid; m < 4096; m += 256) {
            int r = m >> 6, c = m & 63;
            sL[r*68 + c] = P[(i0 + r)*Xd + jb*64 + c];
        }
        __syncthreads();
        for (int j = 0; j < 64; j++) {
            float4 w = *(const float4*)&P[(jb*64 + j)*Xd + k0 + tc*4];
            #pragma unroll
            for (int r = 0; r < 4; r++) {
                float v = sL[(tr*4 + r)*68 + j];
                acc[r][0]+=v*w.x; acc[r][1]+=v*w.y; acc[r][2]+=v*w.z; acc[r][3]+=v*w.w;
            }
        }
        __syncthreads();
    }
    #pragma unroll
    for (int r = 0; r < 4; r++) {
        float4 o = {acc[r][0],acc[r][1],acc[r][2],acc[r][3]};
        *(float4*)&Q[(i0 + tr*4 + r)*Xd + k0 + tc*4] = o;
    }
}

// ---------------- generic chunked linear-recurrence scan ----------------
// V <- V·M + D_k each step.  statesOut (if set) receives the PRE-update state.
// Batches are independent: no cross-CTA sync is ever needed.
template<int BBV>
__global__ __launch_bounds__(256) void scan_kernel(
    const float* __restrict__ M, const float* __restrict__ D,
    const float* __restrict__ init, float* __restrict__ statesOut,
    float* __restrict__ finalOut, int nSteps, int nBG)
{
    constexpr int RT = BBV / 8;                  // rows per thread (8 warps)
    __shared__ float sV[BBV*Xd];
    int chunk = blockIdx.x / nBG;
    int b0 = (blockIdx.x - chunk*nBG) * BBV;
    int tid = threadIdx.x, tr = tid >> 5, tc = tid & 31;

    if (init) {
        const float* ip = init + (chunk*Bd + b0)*Xd;
        for (int i = tid*4; i < BBV*Xd; i += 1024) *(float4*)&sV[i] = *(const float4*)&ip[i];
    } else {
        float4 z = {0.f,0.f,0.f,0.f};
        for (int i = tid*4; i < BBV*Xd; i += 1024) *(float4*)&sV[i] = z;
    }
    __syncthreads();

    for (int k = 0; k < nSteps; k++) {
        int rowbase = ((chunk*nSteps + k)*Bd + b0)*Xd;
        if (statesOut) {
            float* sp = statesOut + rowbase;
            for (int i = tid*4; i < BBV*Xd; i += 1024) *(float4*)&sp[i] = *(const float4*)&sV[i];
        }
        const float* Dp = D + rowbase;
        float acc[RT][8];
        #pragma unroll
        for (int r = 0; r < RT; r++) {
            float4 d0 = *(const float4*)&Dp[(tr*RT + r)*Xd + tc*8];
            float4 d1 = *(const float4*)&Dp[(tr*RT + r)*Xd + tc*8 + 4];
            acc[r][0]=d0.x; acc[r][1]=d0.y; acc[r][2]=d0.z; acc[r][3]=d0.w;
            acc[r][4]=d1.x; acc[r][5]=d1.y; acc[r][6]=d1.z; acc[r][7]=d1.w;
        }
        #pragma unroll 4
        for (int j = 0; j < Xd; j++) {
            float4 m0 = *(const float4*)&M[j*Xd + tc*8];
            float4 m1 = *(const float4*)&M[j*Xd + tc*8 + 4];
            #pragma unroll
            for (int r = 0; r < RT; r++) {
                float v = sV[(tr*RT + r)*Xd + j];
                acc[r][0]+=v*m0.x; acc[r][1]+=v*m0.y; acc[r][2]+=v*m0.z; acc[r][3]+=v*m0.w;
                acc[r][4]+=v*m1.x; acc[r][5]+=v*m1.y; acc[r][6]+=v*m1.z; acc[r][7]+=v*m1.w;
            }
        }
        __syncthreads();                          // all reads of old V done
        #pragma unroll
        for (int r = 0; r < RT; r++) {
            float4 o0 = {acc[r][0],acc[r][1],acc[r][2],acc[r][3]};
            float4 o1 = {acc[r][4],acc[r][5],acc[r][6],acc[r][7]};
            *(float4*)&sV[(tr*RT + r)*Xd + tc*8]     = o0;
            *(float4*)&sV[(tr*RT + r)*Xd + tc*8 + 4] = o1;
        }
        __syncthreads();
    }
    if (finalOut) {
        float* fp = finalOut + (chunk*Bd + b0)*Xd;
        for (int i = tid*4; i < BBV*Xd; i += 1024) *(float4*)&fp[i] = *(const float4*)&sV[i];
    }
}

// ---------------- heads: per-t CTA, fused 2-layer MLPs with sigmoid ----------------
#define SX_STRIDE 260
#define SH_STRIDE 68
#define HEADS_SMEM ((64*SX_STRIDE + 64*SH_STRIDE)*4)

__global__ __launch_bounds__(256) void heads_kernel(
    const float* __restrict__ Cy1_b, const float* __restrict__ Cy2_b,
    const float* __restrict__ Cz1_b, const float* __restrict__ Cz2_b,
    float* __restrict__ outY, float* __restrict__ outZ)
{
    extern __shared__ float sm[];
    float* sX = sm;
    float* sH = sm + 64*SX_STRIDE;
    int t = blockIdx.x, tid = threadIdx.x;

    const float* xp = &g_Xst[t*Bd*Xd];
    for (int i = tid*4; i < Bd*Xd; i += 1024) {
        float4 v = *(const float4*)&xp[i];
        int b = i >> 8, c = i & 255;
        *(float4*)&sX[b*SX_STRIDE + c] = v;
    }
    __syncthreads();

    int tr = tid >> 4, tc = tid & 15;            // 16x16: 4 rows x 4 cols per thread

    // ---------- Y head ----------
    float accY[4][4];
    {
        float4 b2 = *(const float4*)&Cy2_b[tc*4];
        #pragma unroll
        for (int r = 0; r < 4; r++) { accY[r][0]=b2.x; accY[r][1]=b2.y; accY[r][2]=b2.z; accY[r][3]=b2.w; }
    }
    for (int jb = 0; jb < 4; jb++) {
        float h[4][4];
        float4 b1 = *(const float4*)&Cy1_b[jb*64 + tc*4];
        #pragma unroll
        for (int r = 0; r < 4; r++) { h[r][0]=b1.x; h[r][1]=b1.y; h[r][2]=b1.z; h[r][3]=b1.w; }
        #pragma unroll 2
        for (int j = 0; j < Xd; j++) {
            float4 w = *(const float4*)&g_Cy1T[j*Xd + jb*64 + tc*4];
            #pragma unroll
            for (int r = 0; r < 4; r++) {
                float v = sX[(tr*4 + r)*SX_STRIDE + j];
                h[r][0]+=v*w.x; h[r][1]+=v*w.y; h[r][2]+=v*w.z; h[r][3]+=v*w.w;
            }
        }
        __syncthreads();                          // prior sH consumers done
        #pragma unroll
        for (int r = 0; r < 4; r++) {
            float4 o = {fmaxf(h[r][0],0.f),fmaxf(h[r][1],0.f),fmaxf(h[r][2],0.f),fmaxf(h[r][3],0.f)};
            *(float4*)&sH[(tr*4 + r)*SH_STRIDE + tc*4] = o;
        }
        __syncthreads();
        for (int j = 0; j < 64; j++) {
            float4 w = *(const float4*)&g_Cy2T[(jb*64 + j)*YHd + tc*4];
            #pragma unroll
            for (int r = 0; r < 4; r++) {
                float hv = sH[(tr*4 + r)*SH_STRIDE + j];
                accY[r][0]+=hv*w.x; accY[r][1]+=hv*w.y; accY[r][2]+=hv*w.z; accY[r][3]+=hv*w.w;
            }
        }
    }
    #pragma unroll
    for (int r = 0; r < 4; r++) {
        int b = tr*4 + r;
        float4 o = {sigm(accY[r][0]), sigm(accY[r][1]), sigm(accY[r][2]), sigm(accY[r][3])};
        *(float4*)&outY[(b*Td + t)*YHd + tc*4] = o;
    }

    // ---------- Z head ----------
    int rz = tid >> 2, cz = (tid & 3) * 4;       // 64 rows x 4 cols per thread for the 64x16 output
    float accZ[4];
    {
        float4 b2 = *(const float4*)&Cz2_b[cz];
        accZ[0]=b2.x; accZ[1]=b2.y; accZ[2]=b2.z; accZ[3]=b2.w;
    }
    for (int jb = 0; jb < 4; jb++) {
        float h[4][4];
        float4 b1 = *(const float4*)&Cz1_b[jb*64 + tc*4];
        #pragma unroll
        for (int r = 0; r < 4; r++) { h[r][0]=b1.x; h[r][1]=b1.y; h[r][2]=b1.z; h[r][3]=b1.w; }
        #pragma unroll 2
        for (int j = 0; j < Xd; j++) {
            float4 w = *(const float4*)&g_Cz1T[j*Xd + jb*64 + tc*4];
            #pragma unroll
            for (int r = 0; r < 4; r++) {
                float v = sX[(tr*4 + r)*SX_STRIDE + j];
                h[r][0]+=v*w.x; h[r][1]+=v*w.y; h[r][2]+=v*w.z; h[r][3]+=v*w.w;
            }
        }
        __syncthreads();                          // prior sH consumers done
        #pragma unroll
        for (int r = 0; r < 4; r++) {
            float4 o = {fmaxf(h[r][0],0.f),fmaxf(h[r][1],0.f),fmaxf(h[r][2],0.f),fmaxf(h[r][3],0.f)};
            *(float4*)&sH[(tr*4 + r)*SH_STRIDE + tc*4] = o;
        }
        __syncthreads();
        for (int j = 0; j < 64; j++) {
            float4 w = *(const float4*)&g_Cz2T[(jb*64 + j)*ZHd + cz];
            float hv = sH[rz*SH_STRIDE + j];
            accZ[0]+=hv*w.x; accZ[1]+=hv*w.y; accZ[2]+=hv*w.z; accZ[3]+=hv*w.w;
        }
    }
    {
        float4 o = {sigm(accZ[0]), sigm(accZ[1]), sigm(accZ[2]), sigm(accZ[3])};
        *(float4*)&outZ[(rz*Td + t)*ZHd + cz] = o;
    }
}

// ---------------- launch ----------------
extern "C" void kernel_launch(void* const* d_in, const int* in_sizes, int n_in,
                              void* d_out, int out_size)
{
    (void)in_sizes; (void)n_in; (void)out_size;
    const float* y     = (const float*)d_in[0];
    const float* u     = (const float*)d_in[1];
    const float* A_w   = (const float*)d_in[2];
    const float* A_b   = (const float*)d_in[3];
    const float* K_w   = (const float*)d_in[4];
    const float* K_b   = (const float*)d_in[5];
    const float* Bm_w  = (const float*)d_in[6];
    const float* Bm_b  = (const float*)d_in[7];
    const float* Cy1_w = (const float*)d_in[8];
    const float* Cy1_b = (const float*)d_in[9];
    const float* Cy2_w = (const float*)d_in[10];
    const float* Cy2_b = (const float*)d_in[11];
    const float* Cz1_w = (const float*)d_in[12];
    const float* Cz1_b = (const float*)d_in[13];
    const float* Cz2_w = (const float*)d_in[14];
    const float* Cz2_b = (const float*)d_in[15];
    float* outY = (float*)d_out;
    float* outZ = outY + (size_t)Bd*Td*YHd;

    float *pM, *pP0, *pP1, *pDrive, *pE, *pX0, *pX;
    cudaGetSymbolAddress((void**)&pM,  g_M);
    cudaGetSymbolAddress((void**)&pP0, g_P0);
    cudaGetSymbolAddress((void**)&pP1, g_P1);
    cudaGetSymbolAddress((void**)&pDrive, g_drive);
    cudaGetSymbolAddress((void**)&pE,  g_E);
    cudaGetSymbolAddress((void**)&pX0, g_X0);
    cudaGetSymbolAddress((void**)&pX,  g_Xst);

    cudaFuncSetAttribute(heads_kernel, cudaFuncAttributeMaxDynamicSharedMemorySize, HEADS_SMEM);

    setup_kernel<<<256, 256>>>(A_w, A_b, K_w, K_b, Bm_w, Bm_b, Cy1_w, Cz1_w, Cy2_w, Cz2_w);
    drive_kernel<<<Td, 256>>>(y, u);

    // Mc = M^32 by repeated squaring
    matsq_kernel<<<16, 256>>>(pM,  pP0);   // M^2
    matsq_kernel<<<16, 256>>>(pP0, pP1);   // M^4
    matsq_kernel<<<16, 256>>>(pP1, pP0);   // M^8
    matsq_kernel<<<16, 256>>>(pP0, pP1);   // M^16
    matsq_kernel<<<16, 256>>>(pP1, pP0);   // M^32

    // pass 1: per-chunk zero-start recurrences -> chunk end states E_c
    scan_kernel<32><<<NCc*2, 256>>>(pM, pDrive, nullptr, nullptr, pE, Cc, 2);
    // carry: X0_{c+1} = X0_c * M^32 + E_c  (stores pre-update X0_c)
    scan_kernel<8><<<8, 256>>>(pP0, pE, nullptr, pX0, nullptr, NCc, 8);
    // pass 2: re-run each chunk from true X0_c, streaming pre-update states
    scan_kernel<32><<<NCc*2, 256>>>(pM, pDrive, pX0, pX, nullptr, Cc, 2);

    heads_kernel<<<Td, 256, HEADS_SMEM>>>(Cy1_b, Cy2_b, Cz1_b, Cz2_b, outY, outZ);
}